// round 5
// baseline (speedup 1.0000x reference)
#include <cuda_runtime.h>

// Problem constants
#define BB 1024
#define FF 256
#define DD 64

// Persistent scratch (device globals — no allocation allowed)
__device__ __align__(16) float g_trans[2 * FF * DD];   // [2][F][D]
__device__ __align__(16) float g_qkv[3 * FF * DD];     // [3][F][D]
__device__ __align__(16) float g_Mt[FF * FF];          // Mt[j][i] = cross[i,j]*gate[i,j]

// ---------------- packed f32x2 helpers (Blackwell FFMA2) ----------------
__device__ __forceinline__ unsigned long long f32x2_fma(unsigned long long a,
                                                        unsigned long long b,
                                                        unsigned long long c) {
    unsigned long long d;
    asm("fma.rn.f32x2 %0, %1, %2, %3;" : "=l"(d) : "l"(a), "l"(b), "l"(c));
    return d;
}
__device__ __forceinline__ unsigned long long f32x2_pack(float lo, float hi) {
    unsigned long long r;
    asm("mov.b64 %0, {%1, %2};" : "=l"(r) : "f"(lo), "f"(hi));
    return r;
}
__device__ __forceinline__ float2 f32x2_unpack(unsigned long long v) {
    float2 r;
    asm("mov.b64 {%0, %1}, %2;" : "=f"(r.x), "=f"(r.y) : "l"(v));
    return r;
}

// ---------------- kernel 1: projections trans = ind@Wqk, qkv = ind@Wqkv ----------------
// grid FF, block DD. thread e computes column e of row f.
__global__ void k_proj(const float* __restrict__ ind,
                       const float* __restrict__ Wqk,
                       const float* __restrict__ Wqkv) {
    __shared__ float sInd[DD];
    int f = blockIdx.x, e = threadIdx.x;
    sInd[e] = ind[f * DD + e];
    __syncthreads();
#pragma unroll
    for (int n = 0; n < 2; n++) {
        float acc = 0.f;
#pragma unroll 8
        for (int d = 0; d < DD; d++) acc += sInd[d] * Wqk[(n * DD + d) * DD + e];
        g_trans[(n * FF + f) * DD + e] = acc;
    }
#pragma unroll
    for (int n = 0; n < 3; n++) {
        float acc = 0.f;
#pragma unroll 8
        for (int d = 0; d < DD; d++) acc += sInd[d] * Wqkv[(n * DD + d) * DD + e];
        g_qkv[(n * FF + f) * DD + e] = acc;
    }
}

// ---------------- kernel 2: Mt[j][i] = (qkv1[i].qkv0[j]) * (trans0[i].trans1[j] > 0) ----------------
// grid FF (j), block FF (i)
__global__ void k_gate() {
    __shared__ float q0[DD], t1[DD];
    int j = blockIdx.x, i = threadIdx.x;
    if (i < DD) {
        q0[i] = g_qkv[(0 * FF + j) * DD + i];
        t1[i] = g_trans[(1 * FF + j) * DD + i];
    }
    __syncthreads();
    const float4* q1 = (const float4*)&g_qkv[(1 * FF + i) * DD];
    const float4* t0 = (const float4*)&g_trans[(0 * FF + i) * DD];
    float cr = 0.f, lg = 0.f;
#pragma unroll
    for (int d4 = 0; d4 < DD / 4; d4++) {
        float4 a = q1[d4];
        float4 b = t0[d4];
        cr += a.x * q0[d4 * 4 + 0] + a.y * q0[d4 * 4 + 1] + a.z * q0[d4 * 4 + 2] + a.w * q0[d4 * 4 + 3];
        lg += b.x * t1[d4 * 4 + 0] + b.y * t1[d4 * 4 + 1] + b.z * t1[d4 * 4 + 2] + b.w * t1[d4 * 4 + 3];
    }
    g_Mt[j * FF + i] = (lg > 0.f) ? cr : 0.f;
}

// ---------------- kernel 3: per-batch fused s + (M @ diag(s1) qkv2) + epilogue ----------------
// grid BB (b), block 256 threads.
// smem: V[256][64] (s1-scaled qkv2), s1[256], cc[256]
__global__ void __launch_bounds__(256) k_main(const float* __restrict__ feature,
                                              float* __restrict__ out) {
    extern __shared__ float sm[];
    float* V  = sm;                 // FF*DD floats
    float* s1 = sm + FF * DD;       // FF
    float* cc = s1 + FF;            // FF

    int b = blockIdx.x;
    int tid = threadIdx.x;

    // ---- phase A: s[t, b, i] for i = tid ----
    {
        const float4* fr = (const float4*)&feature[(b * FF + tid) * DD];
        const float4* q0 = (const float4*)&g_qkv[(0 * FF + tid) * DD];
        const float4* q1 = (const float4*)&g_qkv[(1 * FF + tid) * DD];
        const float4* q2 = (const float4*)&g_qkv[(2 * FF + tid) * DD];
        float a0 = 0.f, a1 = 0.f, a2 = 0.f;
#pragma unroll
        for (int d4 = 0; d4 < DD / 4; d4++) {
            float4 fv = fr[d4];
            float4 x0 = q0[d4], x1 = q1[d4], x2 = q2[d4];
            a0 += fv.x * x0.x + fv.y * x0.y + fv.z * x0.z + fv.w * x0.w;
            a1 += fv.x * x1.x + fv.y * x1.y + fv.z * x1.z + fv.w * x1.w;
            a2 += fv.x * x2.x + fv.y * x2.y + fv.z * x2.z + fv.w * x2.w;
        }
        s1[tid] = a1;
        cc[tid] = a0 * a2;
    }
    __syncthreads();

    // ---- phase B: V[j][d] = s1[j] * qkv2[j][d] (coalesced float4) ----
    {
        const float4* q2 = (const float4*)(g_qkv + 2 * FF * DD);
        float4* V4 = (float4*)V;
#pragma unroll
        for (int k = 0; k < 16; k++) {
            int idx = tid + k * 256;      // float4 index, 16 float4 per row
            int j = idx >> 4;
            float s = s1[j];
            float4 v = q2[idx];
            v.x *= s; v.y *= s; v.z *= s; v.w *= s;
            V4[idx] = v;
        }
    }
    __syncthreads();

    // ---- phase C: C[i,d] = sum_j Mt[j][i] * V[j][d], 8i x 8d per thread via f32x2 ----
    // d-tile is two strided float4s: {dg*4 .. dg*4+3} and {32+dg*4 .. 32+dg*4+3}.
    // Across a warp the 8 dg values then hit all 32 smem banks exactly once per
    // LDS.128 (conflict-free; ig groups broadcast), unlike the contiguous d0=dg*8
    // mapping which is a structural 2-way conflict.
    int ig = tid >> 3, dg = tid & 7;
    int i0 = ig * 8;
    int d0a = dg * 4, d0b = 32 + dg * 4;

    unsigned long long acc[8][4];
#pragma unroll
    for (int ii = 0; ii < 8; ii++)
#pragma unroll
        for (int dd = 0; dd < 4; dd++) acc[ii][dd] = 0ull;  // packs (0.f, 0.f)

#pragma unroll 2
    for (int j = 0; j < FF; j++) {
        float4 m0 = __ldg((const float4*)&g_Mt[j * FF + i0]);
        float4 m1 = __ldg((const float4*)&g_Mt[j * FF + i0 + 4]);
        float4 v0 = *(const float4*)&V[j * DD + d0a];
        float4 v1 = *(const float4*)&V[j * DD + d0b];

        unsigned long long vv[4];
        vv[0] = f32x2_pack(v0.x, v0.y);
        vv[1] = f32x2_pack(v0.z, v0.w);
        vv[2] = f32x2_pack(v1.x, v1.y);
        vv[3] = f32x2_pack(v1.z, v1.w);

        float m[8] = {m0.x, m0.y, m0.z, m0.w, m1.x, m1.y, m1.z, m1.w};
#pragma unroll
        for (int ii = 0; ii < 8; ii++) {
            unsigned long long mm = f32x2_pack(m[ii], m[ii]);
#pragma unroll
            for (int dd = 0; dd < 4; dd++)
                acc[ii][dd] = f32x2_fma(mm, vv[dd], acc[ii][dd]);
        }
    }

    // ---- epilogue: out[b, i, d] = cc[i] * C[i, d] ----
#pragma unroll
    for (int ii = 0; ii < 8; ii++) {
        float c = cc[i0 + ii];
        float2 r0 = f32x2_unpack(acc[ii][0]);
        float2 r1 = f32x2_unpack(acc[ii][1]);
        float2 r2 = f32x2_unpack(acc[ii][2]);
        float2 r3 = f32x2_unpack(acc[ii][3]);
        float4 o0 = make_float4(c * r0.x, c * r0.y, c * r1.x, c * r1.y);
        float4 o1 = make_float4(c * r2.x, c * r2.y, c * r3.x, c * r3.y);
        float* row = &out[(b * FF + i0 + ii) * DD];
        *(float4*)&row[d0a] = o0;
        *(float4*)&row[d0b] = o1;
    }
}

extern "C" void kernel_launch(void* const* d_in, const int* in_sizes, int n_in,
                              void* d_out, int out_size) {
    const float* feature = (const float*)d_in[0];  // [1024,256,64]
    const float* ind     = (const float*)d_in[1];  // [256,64]
    const float* Wqk     = (const float*)d_in[2];  // [2,64,64]
    const float* Wqkv    = (const float*)d_in[3];  // [3,64,64]
    float* out = (float*)d_out;

    const int smem_bytes = (FF * DD + 2 * FF) * (int)sizeof(float);  // 67584
    static int attr_done = 0;
    if (!attr_done) {
        cudaFuncSetAttribute(k_main, cudaFuncAttributeMaxDynamicSharedMemorySize, smem_bytes);
        attr_done = 1;
    }

    k_proj<<<FF, DD>>>(ind, Wqk, Wqkv);
    k_gate<<<FF, FF>>>();
    k_main<<<BB, 256, smem_bytes>>>(feature, out);
}

// round 11
// speedup vs baseline: 1.5501x; 1.5501x over previous
#include <cuda_runtime.h>
#include <cuda_bf16.h>

// Problem constants
#define BB 1024
#define FF 256
#define DD 64

// ------------------------- persistent device scratch -------------------------
__device__ __align__(16) float g_trans[2 * FF * DD];     // [2][F][D]
__device__ __align__(16) float g_qkv[3 * FF * DD];       // [3][F][D]
__device__ __align__(16) float g_q2t[DD * FF];           // q2 transposed [d][j]
__device__ __align__(16) float g_s1[BB * FF];            // s1[b][j]
__device__ __align__(16) float g_cc[BB * FF];            // s0*s2 [b][i]
// A-operand (gated cross matrix M) in mma.m16n8k16 fragment-linear layout,
// bf16 hi/lo split. Per half: [mt 8][k 16][lane 32][reg 4] uint32 = 64KB.
__device__ __align__(16) unsigned g_AfragHi[2 * 8 * 16 * 32 * 4];
__device__ __align__(16) unsigned g_AfragLo[2 * 8 * 16 * 32 * 4];

// ------------------------- helpers -------------------------
__device__ __forceinline__ unsigned short f2bf(float v) {
    unsigned short r; asm("cvt.rn.bf16.f32 %0, %1;" : "=h"(r) : "f"(v)); return r;
}
// pack two fp32 into bf16x2 hi-part ({lo16: v0, hi16: v1}) and residual lo-part
__device__ __forceinline__ void split2(float v0, float v1, unsigned& hi2, unsigned& lo2) {
    asm("cvt.rn.bf16x2.f32 %0, %1, %2;" : "=r"(hi2) : "f"(v1), "f"(v0));
    float f0 = __uint_as_float(hi2 << 16);
    float f1 = __uint_as_float(hi2 & 0xffff0000u);
    float l0 = v0 - f0, l1 = v1 - f1;
    asm("cvt.rn.bf16x2.f32 %0, %1, %2;" : "=r"(lo2) : "f"(l1), "f"(l0));
}
// HMMA: m16n8k16 row.col bf16 -> fp32 accum (base sm_80+ instruction)
__device__ __forceinline__ void mma4(float* c, const uint4& a, const uint2& b) {
    asm volatile("mma.sync.aligned.m16n8k16.row.col.f32.bf16.bf16.f32 "
                 "{%0,%1,%2,%3}, {%4,%5,%6,%7}, {%8,%9}, {%0,%1,%2,%3};"
                 : "+f"(c[0]), "+f"(c[1]), "+f"(c[2]), "+f"(c[3])
                 : "r"(a.x), "r"(a.y), "r"(a.z), "r"(a.w), "r"(b.x), "r"(b.y));
}

// ---------------- kernel 1: projections, smem-resident ----------------
// grid (16 fgroups, 5 n), block 256
__global__ void __launch_bounds__(256) k_proj(const float* __restrict__ ind,
                                              const float* __restrict__ Wqk,
                                              const float* __restrict__ Wqkv) {
    __shared__ float sW[DD * DD];
    __shared__ float sI[16 * DD];
    int n = blockIdx.y, fg = blockIdx.x, tid = threadIdx.x;
    const float* W = (n < 2) ? (Wqk + n * DD * DD) : (Wqkv + (n - 2) * DD * DD);
#pragma unroll
    for (int it = 0; it < 16; it++) sW[tid + it * 256] = W[tid + it * 256];
#pragma unroll
    for (int it = 0; it < 4; it++) sI[tid + it * 256] = ind[fg * 16 * DD + tid + it * 256];
    __syncthreads();
    int e = tid & 63;
#pragma unroll
    for (int p = 0; p < 4; p++) {
        int fl = (tid >> 6) + p * 4;          // 0..15
        float a0 = 0.f, a1 = 0.f;
#pragma unroll 8
        for (int d = 0; d < DD; d += 2) {
            a0 += sI[fl * DD + d] * sW[d * DD + e];
            a1 += sI[fl * DD + d + 1] * sW[(d + 1) * DD + e];
        }
        float acc = a0 + a1;
        int f = fg * 16 + fl;
        if (n < 2) {
            g_trans[(n * FF + f) * DD + e] = acc;
        } else {
            int nn = n - 2;
            g_qkv[(nn * FF + f) * DD + e] = acc;
            if (nn == 2) g_q2t[e * FF + f] = acc;
        }
    }
}

// ---------------- kernel 2: gated cross matrix -> fragment-linear bf16 hi/lo ----------------
// grid FF (j), block FF (i).  M[i,j] = (qkv1[i].qkv0[j]) * (trans0[i].trans1[j] > 0)
__global__ void __launch_bounds__(FF) k_gate_frag() {
    __shared__ float q0[DD], t1[DD];
    int j = blockIdx.x, i = threadIdx.x;
    if (i < DD) {
        q0[i] = g_qkv[(0 * FF + j) * DD + i];
        t1[i] = g_trans[(1 * FF + j) * DD + i];
    }
    __syncthreads();
    const float4* q1 = (const float4*)&g_qkv[(1 * FF + i) * DD];
    const float4* t0 = (const float4*)&g_trans[(0 * FF + i) * DD];
    float cr = 0.f, lg = 0.f;
#pragma unroll
    for (int d4 = 0; d4 < DD / 4; d4++) {
        float4 a = __ldg(q1 + d4), b = __ldg(t0 + d4);
        cr += a.x * q0[d4 * 4] + a.y * q0[d4 * 4 + 1] + a.z * q0[d4 * 4 + 2] + a.w * q0[d4 * 4 + 3];
        lg += b.x * t1[d4 * 4] + b.y * t1[d4 * 4 + 1] + b.z * t1[d4 * 4 + 2] + b.w * t1[d4 * 4 + 3];
    }
    float m = (lg > 0.f) ? cr : 0.f;
    unsigned short hb = f2bf(m);
    float fh = __uint_as_float(((unsigned)hb) << 16);
    unsigned short lb = f2bf(m - fh);

    // fragment coordinates for A row i (m-dim), col j (k-dim)
    int h    = i >> 7;                 // half
    int mt   = (i >> 4) & 7;           // m16 tile within half
    int k    = j >> 4;                 // k16 step
    int gr   = i & 7;                  // group row
    int lane = gr * 4 + ((j >> 1) & 3);
    int r    = (((j >> 3) & 1) << 1) | ((i >> 3) & 1);  // khigh*2 + rowhigh
    int half = j & 1;
    unsigned idx = ((((unsigned)(h * 8 + mt) * 16 + k) * 32 + lane) * 4 + r) * 2 + half;
    ((unsigned short*)g_AfragHi)[idx] = hb;
    ((unsigned short*)g_AfragLo)[idx] = lb;
}

// ---------------- kernel 3: per-batch scalars s1, cc = s0*s2 ----------------
__global__ void __launch_bounds__(FF) k_s(const float* __restrict__ feature) {
    int b = blockIdx.x, i = threadIdx.x;
    const float4* fr = (const float4*)&feature[((size_t)b * FF + i) * DD];
    const float4* q0 = (const float4*)&g_qkv[(0 * FF + i) * DD];
    const float4* q1 = (const float4*)&g_qkv[(1 * FF + i) * DD];
    const float4* q2 = (const float4*)&g_qkv[(2 * FF + i) * DD];
    float a0 = 0.f, a1 = 0.f, a2 = 0.f;
#pragma unroll
    for (int d4 = 0; d4 < DD / 4; d4++) {
        float4 fv = fr[d4];
        float4 x0 = __ldg(q0 + d4), x1 = __ldg(q1 + d4), x2 = __ldg(q2 + d4);
        a0 += fv.x * x0.x + fv.y * x0.y + fv.z * x0.z + fv.w * x0.w;
        a1 += fv.x * x1.x + fv.y * x1.y + fv.z * x1.z + fv.w * x1.w;
        a2 += fv.x * x2.x + fv.y * x2.y + fv.z * x2.z + fv.w * x2.w;
    }
    g_s1[b * FF + i] = a1;
    g_cc[b * FF + i] = a0 * a2;
}

// ---------------- kernel 4: persistent HMMA bf16x3 batched GEMM ----------------
// grid 296 = 2 halves x 148 slices, block 128 (4 warps).
// smem byte map:
#define S_AHI 0
#define S_ALO 65536
#define S_BHI 131072
#define S_BLO 163840
#define S_S1  196608
#define S_CC  197632
#define SMEM_MAIN 198656

__global__ void __launch_bounds__(128, 1) k_main(float* __restrict__ out) {
    extern __shared__ __align__(16) unsigned char sm[];
    float* s1s = (float*)(sm + S_S1);   // [256]
    float* ccs = (float*)(sm + S_CC);   // [256]
    const uint4* Ah = (const uint4*)(sm + S_AHI);
    const uint4* Al = (const uint4*)(sm + S_ALO);
    const uint2* Bh = (const uint2*)(sm + S_BHI);
    const uint2* Bl = (const uint2*)(sm + S_BLO);

    int tid = threadIdx.x, w = tid >> 5, lane = tid & 31;
    int h = blockIdx.x & 1;
    int s = blockIdx.x >> 1;          // 0..147

    // ---- load A-frag half into smem (once per block) ----
    {
        const uint4* gAh = ((const uint4*)g_AfragHi) + h * 4096;
        const uint4* gAl = ((const uint4*)g_AfragLo) + h * 4096;
        uint4* dAh = (uint4*)(sm + S_AHI);
        uint4* dAl = (uint4*)(sm + S_ALO);
#pragma unroll
        for (int it = 0; it < 32; it++) {
            int idx = tid + it * 128;
            dAh[idx] = __ldg(gAh + idx);
            dAl[idx] = __ldg(gAl + idx);
        }
    }
    __syncthreads();

    int gr = lane >> 2, tig = lane & 3;

    for (int b = s; b < BB; b += 148) {
        // ---- per-batch scalars ----
        s1s[tid]       = g_s1[b * FF + tid];
        s1s[tid + 128] = g_s1[b * FF + tid + 128];
        ccs[tid]       = g_cc[b * FF + tid];
        ccs[tid + 128] = g_cc[b * FF + tid + 128];
        __syncthreads();

        // ---- build B fragments: B[k=j][n=d] = s1[j]*q2t[d][j], hi/lo ----
#pragma unroll
        for (int it = 0; it < 32; it++) {
            int t  = tid + it * 128;        // 0..4095
            int ln = t & 31;
            int k  = (t >> 5) & 15;
            int nt = t >> 9;                // 0..7
            int d  = nt * 8 + (ln >> 2);
            int j0 = k * 16 + 2 * (ln & 3);
            const float* qrow = g_q2t + d * FF;
            float2 va = *(const float2*)(qrow + j0);
            float2 vb = *(const float2*)(qrow + j0 + 8);
            float sa0 = s1s[j0], sa1 = s1s[j0 + 1];
            float sb0 = s1s[j0 + 8], sb1 = s1s[j0 + 9];
            unsigned h0, l0, h1, l1;
            split2(va.x * sa0, va.y * sa1, h0, l0);
            split2(vb.x * sb0, vb.y * sb1, h1, l1);
            int fidx = (nt * 16 + k) * 32 + ln;
            ((uint2*)(sm + S_BHI))[fidx] = make_uint2(h0, h1);
            ((uint2*)(sm + S_BLO))[fidx] = make_uint2(l0, l1);
        }
        __syncthreads();

        // ---- mma: 2 m-tiles x 8 n-tiles x 16 k x 3 passes ----
        float acc[2][8][4];
#pragma unroll
        for (int mt = 0; mt < 2; mt++)
#pragma unroll
            for (int nt = 0; nt < 8; nt++)
#pragma unroll
                for (int q = 0; q < 4; q++) acc[mt][nt][q] = 0.f;

        int wm0 = w * 2, wm1 = w * 2 + 1;
        for (int k = 0; k < 16; k++) {
            uint4 ah0 = Ah[(wm0 * 16 + k) * 32 + lane];
            uint4 ah1 = Ah[(wm1 * 16 + k) * 32 + lane];
            uint4 al0 = Al[(wm0 * 16 + k) * 32 + lane];
            uint4 al1 = Al[(wm1 * 16 + k) * 32 + lane];
#pragma unroll
            for (int nt = 0; nt < 8; nt++) {
                uint2 bh = Bh[(nt * 16 + k) * 32 + lane];
                uint2 bl = Bl[(nt * 16 + k) * 32 + lane];
                mma4(acc[0][nt], ah0, bh);
                mma4(acc[0][nt], ah0, bl);
                mma4(acc[0][nt], al0, bh);
                mma4(acc[1][nt], ah1, bh);
                mma4(acc[1][nt], ah1, bl);
                mma4(acc[1][nt], al1, bh);
            }
        }

        // ---- epilogue: scale by cc and store ----
#pragma unroll
        for (int mt = 0; mt < 2; mt++) {
            int i0 = h * 128 + (w * 2 + mt) * 16 + gr;
            int i1 = i0 + 8;
            float c0 = ccs[i0], c1 = ccs[i1];
            float* row0 = out + ((size_t)b * FF + i0) * DD;
            float* row1 = out + ((size_t)b * FF + i1) * DD;
#pragma unroll
            for (int nt = 0; nt < 8; nt++) {
                int d0 = nt * 8 + 2 * tig;
                *(float2*)(row0 + d0) = make_float2(c0 * acc[mt][nt][0], c0 * acc[mt][nt][1]);
                *(float2*)(row1 + d0) = make_float2(c1 * acc[mt][nt][2], c1 * acc[mt][nt][3]);
            }
        }
        __syncthreads();   // protect B/s1/cc for next batch
    }
}

// ---------------- host launcher ----------------
extern "C" void kernel_launch(void* const* d_in, const int* in_sizes, int n_in,
                              void* d_out, int out_size) {
    const float* feature = (const float*)d_in[0];  // [1024,256,64]
    const float* ind     = (const float*)d_in[1];  // [256,64]
    const float* Wqk     = (const float*)d_in[2];  // [2,64,64]
    const float* Wqkv    = (const float*)d_in[3];  // [3,64,64]
    float* out = (float*)d_out;

    static int attr_done = 0;
    if (!attr_done) {
        cudaFuncSetAttribute(k_main, cudaFuncAttributeMaxDynamicSharedMemorySize, SMEM_MAIN);
        attr_done = 1;
    }

    k_proj<<<dim3(16, 5), 256>>>(ind, Wqk, Wqkv);
    k_gate_frag<<<FF, FF>>>();
    k_s<<<BB, FF>>>(feature);
    k_main<<<296, 128, SMEM_MAIN>>>(out);
}

// round 17
// speedup vs baseline: 1.6075x; 1.0370x over previous
#include <cuda_runtime.h>
#include <cuda_bf16.h>

// Problem constants
#define BB 1024
#define FF 256
#define DD 64

// ------------------------- persistent device scratch -------------------------
__device__ __align__(16) float g_trans[2 * FF * DD];     // [2][F][D]
__device__ __align__(16) float g_qkv[3 * FF * DD];       // [3][F][D]
__device__ __align__(16) float g_q2t[DD * FF];           // q2 transposed [d][j]
__device__ __align__(16) float g_s1[BB * FF];            // s1[b][j]
__device__ __align__(16) float g_cc[BB * FF];            // s0*s2 [b][i]
// A-operand (gated cross matrix M) in mma.m16n8k16 fragment-linear layout,
// bf16 hi/lo split. Per half: [mt 8][k 16][lane 32][reg 4] uint32 = 64KB.
__device__ __align__(16) unsigned g_AfragHi[2 * 8 * 16 * 32 * 4];
__device__ __align__(16) unsigned g_AfragLo[2 * 8 * 16 * 32 * 4];

// ------------------------- helpers -------------------------
__device__ __forceinline__ unsigned short f2bf(float v) {
    unsigned short r; asm("cvt.rn.bf16.f32 %0, %1;" : "=h"(r) : "f"(v)); return r;
}
// pack two fp32 into bf16x2 hi-part ({lo16: v0, hi16: v1}) and residual lo-part
__device__ __forceinline__ void split2(float v0, float v1, unsigned& hi2, unsigned& lo2) {
    asm("cvt.rn.bf16x2.f32 %0, %1, %2;" : "=r"(hi2) : "f"(v1), "f"(v0));
    float f0 = __uint_as_float(hi2 << 16);
    float f1 = __uint_as_float(hi2 & 0xffff0000u);
    float l0 = v0 - f0, l1 = v1 - f1;
    asm("cvt.rn.bf16x2.f32 %0, %1, %2;" : "=r"(lo2) : "f"(l1), "f"(l0));
}
// HMMA: m16n8k16 row.col bf16 -> fp32 accum (base sm_80+ instruction)
__device__ __forceinline__ void mma4(float* c, const uint4& a, const uint2& b) {
    asm volatile("mma.sync.aligned.m16n8k16.row.col.f32.bf16.bf16.f32 "
                 "{%0,%1,%2,%3}, {%4,%5,%6,%7}, {%8,%9}, {%0,%1,%2,%3};"
                 : "+f"(c[0]), "+f"(c[1]), "+f"(c[2]), "+f"(c[3])
                 : "r"(a.x), "r"(a.y), "r"(a.z), "r"(a.w), "r"(b.x), "r"(b.y));
}

// ---------------- kernel 1: projections, smem-resident ----------------
// grid (16 fgroups, 5 n), block 256
__global__ void __launch_bounds__(256) k_proj(const float* __restrict__ ind,
                                              const float* __restrict__ Wqk,
                                              const float* __restrict__ Wqkv) {
    __shared__ float sW[DD * DD];
    __shared__ float sI[16 * DD];
    int n = blockIdx.y, fg = blockIdx.x, tid = threadIdx.x;
    const float* W = (n < 2) ? (Wqk + n * DD * DD) : (Wqkv + (n - 2) * DD * DD);
#pragma unroll
    for (int it = 0; it < 16; it++) sW[tid + it * 256] = W[tid + it * 256];
#pragma unroll
    for (int it = 0; it < 4; it++) sI[tid + it * 256] = ind[fg * 16 * DD + tid + it * 256];
    __syncthreads();
    int e = tid & 63;
#pragma unroll
    for (int p = 0; p < 4; p++) {
        int fl = (tid >> 6) + p * 4;          // 0..15
        float a0 = 0.f, a1 = 0.f;
#pragma unroll 8
        for (int d = 0; d < DD; d += 2) {
            a0 += sI[fl * DD + d] * sW[d * DD + e];
            a1 += sI[fl * DD + d + 1] * sW[(d + 1) * DD + e];
        }
        float acc = a0 + a1;
        int f = fg * 16 + fl;
        if (n < 2) {
            g_trans[(n * FF + f) * DD + e] = acc;
        } else {
            int nn = n - 2;
            g_qkv[(nn * FF + f) * DD + e] = acc;
            if (nn == 2) g_q2t[e * FF + f] = acc;
        }
    }
}

// ---------------- kernel 2: gated cross matrix -> fragment-linear bf16 hi/lo ----------------
// grid (16 k-steps, 2 halves), block 256 (= 128 i-rows x 2 j-groups).
// Computes M[i, j] for i in half, j in k-step tile; stages fragment shorts in
// smem; writes out as contiguous 512B u32 runs (fully coalesced).
__global__ void __launch_bounds__(256) k_gate_frag() {
    __shared__ float q0s[16 * DD], t1s[16 * DD];
    __shared__ unsigned short sHi[2048], sLo[2048];
    int kk = blockIdx.x, h = blockIdx.y;
    int tid = threadIdx.x;

    // load the 16-row j tile of q0 / t1 (coalesced)
#pragma unroll
    for (int it = 0; it < 4; it++) {
        int x = tid + it * 256;
        q0s[x] = g_qkv[(0 * FF + kk * 16) * DD + x];
        t1s[x] = g_trans[(1 * FF + kk * 16) * DD + x];
    }
    __syncthreads();

    int ip = tid & 127, jg = tid >> 7;   // i-local, j-group (8 j's each)
    int i = h * 128 + ip;
    const float4* q1 = (const float4*)&g_qkv[(1 * FF + i) * DD];
    const float4* t0 = (const float4*)&g_trans[(0 * FF + i) * DD];

    float cr[8], lg[8];
#pragma unroll
    for (int jv = 0; jv < 8; jv++) { cr[jv] = 0.f; lg[jv] = 0.f; }
#pragma unroll
    for (int d4 = 0; d4 < DD / 4; d4++) {
        float4 a = __ldg(q1 + d4), bmat = __ldg(t0 + d4);
#pragma unroll
        for (int jv = 0; jv < 8; jv++) {
            const float* qr = &q0s[(jg * 8 + jv) * DD + d4 * 4];
            const float* tr = &t1s[(jg * 8 + jv) * DD + d4 * 4];
            cr[jv] += a.x * qr[0] + a.y * qr[1] + a.z * qr[2] + a.w * qr[3];
            lg[jv] += bmat.x * tr[0] + bmat.y * tr[1] + bmat.z * tr[2] + bmat.w * tr[3];
        }
    }

    int mt = ip >> 4, gr = ip & 7, il8 = (ip >> 3) & 1;
#pragma unroll
    for (int jv = 0; jv < 8; jv++) {
        float m = (lg[jv] > 0.f) ? cr[jv] : 0.f;
        unsigned short hb = f2bf(m);
        float fh = __uint_as_float(((unsigned)hb) << 16);
        unsigned short lb = f2bf(m - fh);
        int lane = gr * 4 + (jv >> 1);
        int r = jg * 2 + il8;
        int sidx = ((mt * 32 + lane) * 4 + r) * 2 + (jv & 1);
        sHi[sidx] = hb;
        sLo[sidx] = lb;
    }
    __syncthreads();

    // coalesced copy out: 1024 u32 hi + 1024 u32 lo, in 8 runs of 512B per image
    const unsigned* sh32 = (const unsigned*)sHi;
    const unsigned* sl32 = (const unsigned*)sLo;
#pragma unroll
    for (int it = 0; it < 4; it++) {
        int idx = tid + it * 256;        // 0..1023
        int mt2 = idx >> 7, off = idx & 127;
        unsigned gidx = (unsigned)(((h * 8 + mt2) * 16 + kk) * 128 + off);
        g_AfragHi[gidx] = sh32[idx];
        g_AfragLo[gidx] = sl32[idx];
    }
}

// ---------------- kernel 3: per-batch scalars s1, cc = s0*s2 ----------------
__global__ void __launch_bounds__(FF) k_s(const float* __restrict__ feature) {
    int b = blockIdx.x, i = threadIdx.x;
    const float4* fr = (const float4*)&feature[((size_t)b * FF + i) * DD];
    const float4* q0 = (const float4*)&g_qkv[(0 * FF + i) * DD];
    const float4* q1 = (const float4*)&g_qkv[(1 * FF + i) * DD];
    const float4* q2 = (const float4*)&g_qkv[(2 * FF + i) * DD];
    float a0 = 0.f, a1 = 0.f, a2 = 0.f;
#pragma unroll
    for (int d4 = 0; d4 < DD / 4; d4++) {
        float4 fv = fr[d4];
        float4 x0 = __ldg(q0 + d4), x1 = __ldg(q1 + d4), x2 = __ldg(q2 + d4);
        a0 += fv.x * x0.x + fv.y * x0.y + fv.z * x0.z + fv.w * x0.w;
        a1 += fv.x * x1.x + fv.y * x1.y + fv.z * x1.z + fv.w * x1.w;
        a2 += fv.x * x2.x + fv.y * x2.y + fv.z * x2.z + fv.w * x2.w;
    }
    g_s1[b * FF + i] = a1;
    g_cc[b * FF + i] = a0 * a2;
}

// ---------------- kernel 4: persistent HMMA bf16x3 batched GEMM ----------------
// grid 296 = 2 halves x 148 slices, block 256 (8 warps, warp = m-tile).
// smem byte map:
#define S_AHI 0
#define S_ALO 65536
#define S_BHI 131072
#define S_BLO 163840
#define S_S1  196608
#define S_CC  197632
#define SMEM_MAIN 198656

__global__ void __launch_bounds__(256, 1) k_main(float* __restrict__ out) {
    extern __shared__ __align__(16) unsigned char sm[];
    float* s1s = (float*)(sm + S_S1);   // [256]
    float* ccs = (float*)(sm + S_CC);   // [256]
    const uint4* Ah = (const uint4*)(sm + S_AHI);
    const uint4* Al = (const uint4*)(sm + S_ALO);
    const uint2* Bh = (const uint2*)(sm + S_BHI);
    const uint2* Bl = (const uint2*)(sm + S_BLO);

    int tid = threadIdx.x, w = tid >> 5, lane = tid & 31;
    int h = blockIdx.x & 1;
    int s = blockIdx.x >> 1;          // 0..147

    // ---- load A-frag half into smem (once per block) ----
    {
        const uint4* gAh = ((const uint4*)g_AfragHi) + h * 4096;
        const uint4* gAl = ((const uint4*)g_AfragLo) + h * 4096;
        uint4* dAh = (uint4*)(sm + S_AHI);
        uint4* dAl = (uint4*)(sm + S_ALO);
#pragma unroll
        for (int it = 0; it < 16; it++) {
            int idx = tid + it * 256;
            dAh[idx] = __ldg(gAh + idx);
            dAl[idx] = __ldg(gAl + idx);
        }
    }
    __syncthreads();

    int gr = lane >> 2, tig = lane & 3;

    for (int b = s; b < BB; b += 148) {
        // ---- per-batch scalars ----
        s1s[tid] = g_s1[b * FF + tid];
        ccs[tid] = g_cc[b * FF + tid];
        __syncthreads();

        // ---- build B fragments: B[k=j][n=d] = s1[j]*q2t[d][j], hi/lo ----
#pragma unroll
        for (int it = 0; it < 16; it++) {
            int t  = tid + it * 256;        // 0..4095
            int ln = t & 31;
            int k  = (t >> 5) & 15;
            int nt = t >> 9;                // 0..7
            int d  = nt * 8 + (ln >> 2);
            int j0 = k * 16 + 2 * (ln & 3);
            const float* qrow = g_q2t + d * FF;
            float2 va = *(const float2*)(qrow + j0);
            float2 vb = *(const float2*)(qrow + j0 + 8);
            float sa0 = s1s[j0], sa1 = s1s[j0 + 1];
            float sb0 = s1s[j0 + 8], sb1 = s1s[j0 + 9];
            unsigned h0, l0, h1, l1;
            split2(va.x * sa0, va.y * sa1, h0, l0);
            split2(vb.x * sb0, vb.y * sb1, h1, l1);
            int fidx = (nt * 16 + k) * 32 + ln;
            ((uint2*)(sm + S_BHI))[fidx] = make_uint2(h0, h1);
            ((uint2*)(sm + S_BLO))[fidx] = make_uint2(l0, l1);
        }
        __syncthreads();

        // ---- mma: warp owns m-tile w; 8 n-tiles x 16 k x 3 passes ----
        float acc[8][4];
#pragma unroll
        for (int nt = 0; nt < 8; nt++)
#pragma unroll
            for (int q = 0; q < 4; q++) acc[nt][q] = 0.f;

        for (int k = 0; k < 16; k++) {
            uint4 ah = Ah[(w * 16 + k) * 32 + lane];
            uint4 al = Al[(w * 16 + k) * 32 + lane];
#pragma unroll
            for (int nt = 0; nt < 8; nt++) {
                uint2 bh = Bh[(nt * 16 + k) * 32 + lane];
                uint2 bl = Bl[(nt * 16 + k) * 32 + lane];
                mma4(acc[nt], ah, bh);
                mma4(acc[nt], ah, bl);
                mma4(acc[nt], al, bh);
            }
        }

        // ---- epilogue: scale by cc (GLOBAL i index incl. half offset) and store ----
        {
            int il = h * 128 + w * 16 + gr;     // global i of acc row 0
            float c0 = ccs[il], c1 = ccs[il + 8];
            float* row0 = out + ((size_t)b * FF + il) * DD;
            float* row1 = out + ((size_t)b * FF + il + 8) * DD;
#pragma unroll
            for (int nt = 0; nt < 8; nt++) {
                int d0 = nt * 8 + 2 * tig;
                *(float2*)(row0 + d0) = make_float2(c0 * acc[nt][0], c0 * acc[nt][1]);
                *(float2*)(row1 + d0) = make_float2(c1 * acc[nt][2], c1 * acc[nt][3]);
            }
        }
        __syncthreads();   // protect B/s1/cc for next batch
    }
}

// ---------------- host launcher ----------------
extern "C" void kernel_launch(void* const* d_in, const int* in_sizes, int n_in,
                              void* d_out, int out_size) {
    const float* feature = (const float*)d_in[0];  // [1024,256,64]
    const float* ind     = (const float*)d_in[1];  // [256,64]
    const float* Wqk     = (const float*)d_in[2];  // [2,64,64]
    const float* Wqkv    = (const float*)d_in[3];  // [3,64,64]
    float* out = (float*)d_out;

    static int attr_done = 0;
    if (!attr_done) {
        cudaFuncSetAttribute(k_main, cudaFuncAttributeMaxDynamicSharedMemorySize, SMEM_MAIN);
        attr_done = 1;
    }

    k_proj<<<dim3(16, 5), 256>>>(ind, Wqk, Wqkv);
    k_gate_frag<<<dim3(16, 2), 256>>>();
    k_s<<<BB, FF>>>(feature);
    k_main<<<296, 256, SMEM_MAIN>>>(out);
}